// round 1
// baseline (speedup 1.0000x reference)
#include <cuda_runtime.h>
#include <cuda_bf16.h>
#include <math.h>

#define N_PANO 50000
#define N_FP   10000
#define D_IN   128
#define D_FP   64
#define HID    128
#define OUT_D  64
#define E_PP   800000
#define E_PF   50000

// ---------------- device scratch (static, no allocation) ----------------
__device__ float g_h[N_PANO * HID];     // layer activations
__device__ float g_hs[N_PANO * HID];    // hs (also reused 64-wide for translate)
__device__ float g_lin[N_PANO * HID];   // linear branch
__device__ float g_acc[N_PANO * HID];   // edge aggregation accumulator (reused for fp)
__device__ float g_es[N_PANO];
__device__ float g_ed[N_PANO];
__device__ float g_edfp[N_FP];
__device__ float g_den[N_PANO];         // softmax denominators (reused for fp)
__device__ float g_wc[704];             // composed attention vectors

// ---------------- compose: w = W @ a  (tiny) ----------------
__global__ void compose_kernel(const float* __restrict__ Ws0, const float* __restrict__ as0,
                               const float* __restrict__ Wd0, const float* __restrict__ ad0,
                               const float* __restrict__ Ws1, const float* __restrict__ as1,
                               const float* __restrict__ Wd1, const float* __restrict__ ad1,
                               const float* __restrict__ Wts, const float* __restrict__ ats,
                               const float* __restrict__ Wtd, const float* __restrict__ atd) {
    int b = blockIdx.x, t = threadIdx.x;
    if (b == 0) {
        if (t < 128) {
            float s = 0.f;
            #pragma unroll 8
            for (int n = 0; n < 128; n++) s += Ws0[t * 128 + n] * as0[n];
            g_wc[t] = s;
        } else {
            int i = t - 128; float s = 0.f;
            #pragma unroll 8
            for (int n = 0; n < 128; n++) s += Wd0[i * 128 + n] * ad0[n];
            g_wc[128 + i] = s;
        }
    } else if (b == 1) {
        if (t < 128) {
            float s = 0.f;
            #pragma unroll 8
            for (int n = 0; n < 128; n++) s += Ws1[t * 128 + n] * as1[n];
            g_wc[256 + t] = s;
        } else {
            int i = t - 128; float s = 0.f;
            #pragma unroll 8
            for (int n = 0; n < 128; n++) s += Wd1[i * 128 + n] * ad1[n];
            g_wc[384 + i] = s;
        }
    } else {
        if (t < 128) {
            float s = 0.f;
            #pragma unroll 8
            for (int n = 0; n < 64; n++) s += Wts[t * 64 + n] * ats[n];
            g_wc[512 + t] = s;
        } else if (t < 192) {
            int i = t - 128; float s = 0.f;
            #pragma unroll 8
            for (int n = 0; n < 64; n++) s += Wtd[i * 64 + n] * atd[n];
            g_wc[640 + i] = s;
        }
    }
}

// ---------------- fp32 GEMM: C[M,N] = A[M,128] @ B[128,N], N in {64,128} ----------------
template<int N>
__global__ void __launch_bounds__(256) gemm_kernel(const float* __restrict__ A,
                                                   const float* __restrict__ B,
                                                   float* __restrict__ C, int M) {
    constexpr int BM = 64, BK = 32;
    constexpr int NH = N / 64;          // 1 or 2 column halves of 64
    __shared__ float As[BM * 36];
    __shared__ float Bs[BK * N];
    const int tid = threadIdx.x;
    const int m0 = blockIdx.x * BM;
    const int tx = tid & 15, ty = tid >> 4;

    float acc[4][NH * 4];
    #pragma unroll
    for (int i = 0; i < 4; i++)
        #pragma unroll
        for (int j = 0; j < NH * 4; j++) acc[i][j] = 0.f;

    for (int k0 = 0; k0 < 128; k0 += BK) {
        // load A tile (BM x BK), zero-pad out of range
        #pragma unroll
        for (int l = 0; l < 2; l++) {
            int idx = tid + l * 256;          // 0..511 float4s
            int r = idx >> 3;
            int c = (idx & 7) * 4;
            float4 v = make_float4(0.f, 0.f, 0.f, 0.f);
            if (m0 + r < M) v = *(const float4*)&A[(size_t)(m0 + r) * 128 + k0 + c];
            *(float4*)&As[r * 36 + c] = v;
        }
        // load B tile (BK x N) — contiguous in global
        #pragma unroll
        for (int l = 0; l < (BK * N) / 1024; l++) {
            int idx = (tid + l * 256) * 4;
            *(float4*)&Bs[idx] = *(const float4*)&B[k0 * N + idx];
        }
        __syncthreads();
        #pragma unroll 8
        for (int k = 0; k < BK; k++) {
            float a0 = As[(ty * 4 + 0) * 36 + k];
            float a1 = As[(ty * 4 + 1) * 36 + k];
            float a2 = As[(ty * 4 + 2) * 36 + k];
            float a3 = As[(ty * 4 + 3) * 36 + k];
            #pragma unroll
            for (int h = 0; h < NH; h++) {
                float4 bv = *(const float4*)&Bs[k * N + h * 64 + tx * 4];
                float bf[4] = {bv.x, bv.y, bv.z, bv.w};
                #pragma unroll
                for (int j = 0; j < 4; j++) {
                    acc[0][h * 4 + j] += a0 * bf[j];
                    acc[1][h * 4 + j] += a1 * bf[j];
                    acc[2][h * 4 + j] += a2 * bf[j];
                    acc[3][h * 4 + j] += a3 * bf[j];
                }
            }
        }
        __syncthreads();
    }
    #pragma unroll
    for (int i = 0; i < 4; i++) {
        int r = m0 + ty * 4 + i;
        if (r < M) {
            #pragma unroll
            for (int h = 0; h < NH; h++) {
                float4 v = make_float4(acc[i][h * 4 + 0], acc[i][h * 4 + 1],
                                       acc[i][h * 4 + 2], acc[i][h * 4 + 3]);
                *(float4*)&C[(size_t)r * N + h * 64 + tx * 4] = v;
            }
        }
    }
}

// ---------------- GEMV: two dots per row (es, ed) ----------------
__global__ void gemv2_kernel(const float* __restrict__ X, const float* __restrict__ wa,
                             const float* __restrict__ wb,
                             float* __restrict__ ea, float* __restrict__ eb, int M) {
    int gw = (blockIdx.x * blockDim.x + threadIdx.x) >> 5;
    int lane = threadIdx.x & 31;
    if (gw >= M) return;
    float4 x = *(const float4*)&X[(size_t)gw * 128 + lane * 4];
    float4 a = *(const float4*)&wa[lane * 4];
    float4 b = *(const float4*)&wb[lane * 4];
    float sa = x.x * a.x + x.y * a.y + x.z * a.z + x.w * a.w;
    float sb = x.x * b.x + x.y * b.y + x.z * b.z + x.w * b.w;
    #pragma unroll
    for (int o = 16; o; o >>= 1) {
        sa += __shfl_xor_sync(0xFFFFFFFFu, sa, o);
        sb += __shfl_xor_sync(0xFFFFFFFFu, sb, o);
    }
    if (lane == 0) { ea[gw] = sa; eb[gw] = sb; }
}

template<int D>
__global__ void gemv1_kernel(const float* __restrict__ X, const float* __restrict__ w,
                             float* __restrict__ out, int M) {
    int gw = (blockIdx.x * blockDim.x + threadIdx.x) >> 5;
    int lane = threadIdx.x & 31;
    if (gw >= M) return;
    float s;
    if (D == 128) {
        float4 x = *(const float4*)&X[(size_t)gw * 128 + lane * 4];
        float4 a = *(const float4*)&w[lane * 4];
        s = x.x * a.x + x.y * a.y + x.z * a.z + x.w * a.w;
    } else {
        float2 x = *(const float2*)&X[(size_t)gw * 64 + lane * 2];
        float2 a = *(const float2*)&w[lane * 2];
        s = x.x * a.x + x.y * a.y;
    }
    #pragma unroll
    for (int o = 16; o; o >>= 1) s += __shfl_xor_sync(0xFFFFFFFFu, s, o);
    if (lane == 0) out[gw] = s;
}

// ---------------- zeroing (graph-replay safe re-init) ----------------
__global__ void zero_pano_kernel() {
    int i = blockIdx.x * blockDim.x + threadIdx.x;   // 1,600,000 exactly
    ((float4*)g_acc)[i] = make_float4(0.f, 0.f, 0.f, 0.f);
    if (i < N_PANO / 4) ((float4*)g_den)[i] = make_float4(0.f, 0.f, 0.f, 0.f);
}
__global__ void zero_fp_kernel() {
    int i = blockIdx.x * blockDim.x + threadIdx.x;   // 160,000 exactly
    ((float4*)g_acc)[i] = make_float4(0.f, 0.f, 0.f, 0.f);
    if (i < N_FP / 4) ((float4*)g_den)[i] = make_float4(0.f, 0.f, 0.f, 0.f);
}

// ---------------- edge passes ----------------
__global__ void __launch_bounds__(256) edge_pp_kernel(const int* __restrict__ src,
                                                      const int* __restrict__ dst) {
    int gw = (blockIdx.x * blockDim.x + threadIdx.x) >> 5;
    int lane = threadIdx.x & 31;
    if (gw >= E_PP) return;
    int s = __ldg(&src[gw]);
    int d = __ldg(&dst[gw]);
    float ez = g_es[s] + g_ed[d];
    float e = ez > 0.f ? ez : 0.2f * ez;
    float ex = __expf(e);
    float4 h = *(const float4*)&g_hs[(size_t)s * 128 + lane * 4];
    float* p = &g_acc[(size_t)d * 128 + lane * 4];
    asm volatile("red.global.add.v4.f32 [%0], {%1,%2,%3,%4};"
                 :: "l"(p), "f"(h.x * ex), "f"(h.y * ex), "f"(h.z * ex), "f"(h.w * ex)
                 : "memory");
    if (lane == 0) atomicAdd(&g_den[d], ex);
}

__global__ void __launch_bounds__(256) edge_pf_kernel(const int* __restrict__ src,
                                                      const int* __restrict__ dst) {
    int gw = (blockIdx.x * blockDim.x + threadIdx.x) >> 5;
    int lane = threadIdx.x & 31;
    if (gw >= E_PF) return;
    int s = __ldg(&src[gw]);
    int d = __ldg(&dst[gw]);
    float ez = g_es[s] + g_edfp[d];
    float e = ez > 0.f ? ez : 0.2f * ez;
    float ex = __expf(e);
    float2 h = *(const float2*)&g_hs[(size_t)s * 64 + lane * 2];
    float* p = &g_acc[(size_t)d * 64 + lane * 2];
    asm volatile("red.global.add.v2.f32 [%0], {%1,%2};"
                 :: "l"(p), "f"(h.x * ex), "f"(h.y * ex)
                 : "memory");
    if (lane == 0) atomicAdd(&g_den[d], ex);
}

// ---------------- finalize ----------------
__global__ void finalize_layer_kernel(const float* __restrict__ b, const float* __restrict__ Lb) {
    int i = blockIdx.x * blockDim.x + threadIdx.x;   // 1,600,000 float4s
    int row = i >> 5;
    int c4 = (i & 31) * 4;
    float den = g_den[row];
    float inv = den > 0.f ? 1.f / den : 0.f;
    float4 a = ((const float4*)g_acc)[i];
    float4 l = ((const float4*)g_lin)[i];
    float4 bb = *(const float4*)&b[c4];
    float4 lb = *(const float4*)&Lb[c4];
    float4 r;
    r.x = fmaxf(a.x * inv + bb.x + l.x + lb.x, 0.f);
    r.y = fmaxf(a.y * inv + bb.y + l.y + lb.y, 0.f);
    r.z = fmaxf(a.z * inv + bb.z + l.z + lb.z, 0.f);
    r.w = fmaxf(a.w * inv + bb.w + l.w + lb.w, 0.f);
    ((float4*)g_h)[i] = r;
}

__global__ void final_fp_kernel(const float* __restrict__ bt, float* __restrict__ out) {
    int i = blockIdx.x * blockDim.x + threadIdx.x;   // 160,000 float4s
    int row = i >> 4;
    int c4 = (i & 15) * 4;
    float den = g_den[row];
    float inv = den > 0.f ? 1.f / den : 0.f;
    float4 a = ((const float4*)g_acc)[i];
    float4 bb = *(const float4*)&bt[c4];
    float4 r;
    r.x = a.x * inv + bb.x;
    r.y = a.y * inv + bb.y;
    r.z = a.z * inv + bb.z;
    r.w = a.w * inv + bb.w;
    ((float4*)out)[i] = r;
}

// ---------------- launch ----------------
extern "C" void kernel_launch(void* const* d_in, const int* in_sizes, int n_in,
                              void* d_out, int out_size) {
    const float* x_pano = (const float*)d_in[0];
    const float* x_fp   = (const float*)d_in[1];
    const float* Ws0 = (const float*)d_in[2];
    const float* Wd0 = (const float*)d_in[3];
    const float* as0 = (const float*)d_in[4];
    const float* ad0 = (const float*)d_in[5];
    const float* b0  = (const float*)d_in[6];
    const float* Lw0 = (const float*)d_in[7];
    const float* Lb0 = (const float*)d_in[8];
    const float* Ws1 = (const float*)d_in[9];
    const float* Wd1 = (const float*)d_in[10];
    const float* as1 = (const float*)d_in[11];
    const float* ad1 = (const float*)d_in[12];
    const float* b1  = (const float*)d_in[13];
    const float* Lw1 = (const float*)d_in[14];
    const float* Lb1 = (const float*)d_in[15];
    const float* Wts = (const float*)d_in[16];
    const float* Wtd = (const float*)d_in[17];
    const float* ats = (const float*)d_in[18];
    const float* atd = (const float*)d_in[19];
    const float* bt  = (const float*)d_in[20];
    const int* edge_pp = (const int*)d_in[21];
    const int* pf_src  = (const int*)d_in[22];
    const int* pf_dst  = (const int*)d_in[23];
    const int* pp_src = edge_pp;
    const int* pp_dst = edge_pp + E_PP;

    float *p_h, *p_hs, *p_lin, *p_es, *p_ed, *p_edfp, *p_wc;
    cudaGetSymbolAddress((void**)&p_h,   g_h);
    cudaGetSymbolAddress((void**)&p_hs,  g_hs);
    cudaGetSymbolAddress((void**)&p_lin, g_lin);
    cudaGetSymbolAddress((void**)&p_es,  g_es);
    cudaGetSymbolAddress((void**)&p_ed,  g_ed);
    cudaGetSymbolAddress((void**)&p_edfp, g_edfp);
    cudaGetSymbolAddress((void**)&p_wc,  g_wc);

    const int GEMM_BLKS = (N_PANO + 63) / 64;   // 782

    compose_kernel<<<3, 256>>>(Ws0, as0, Wd0, ad0, Ws1, as1, Wd1, ad1, Wts, ats, Wtd, atd);

    // ---- layer 0 ----
    gemm_kernel<128><<<GEMM_BLKS, 256>>>(x_pano, Ws0, p_hs, N_PANO);
    gemm_kernel<128><<<GEMM_BLKS, 256>>>(x_pano, Lw0, p_lin, N_PANO);
    gemv2_kernel<<<6250, 256>>>(x_pano, p_wc + 0, p_wc + 128, p_es, p_ed, N_PANO);
    zero_pano_kernel<<<6250, 256>>>();
    edge_pp_kernel<<<100000, 256>>>(pp_src, pp_dst);
    finalize_layer_kernel<<<6250, 256>>>(b0, Lb0);

    // ---- layer 1 ----
    gemm_kernel<128><<<GEMM_BLKS, 256>>>(p_h, Ws1, p_hs, N_PANO);
    gemm_kernel<128><<<GEMM_BLKS, 256>>>(p_h, Lw1, p_lin, N_PANO);
    gemv2_kernel<<<6250, 256>>>(p_h, p_wc + 256, p_wc + 384, p_es, p_ed, N_PANO);
    zero_pano_kernel<<<6250, 256>>>();
    edge_pp_kernel<<<100000, 256>>>(pp_src, pp_dst);
    finalize_layer_kernel<<<6250, 256>>>(b1, Lb1);

    // ---- translate pano -> footprint ----
    gemm_kernel<64><<<GEMM_BLKS, 256>>>(p_h, Wts, p_hs, N_PANO);
    gemv1_kernel<128><<<6250, 256>>>(p_h, p_wc + 512, p_es, N_PANO);
    gemv1_kernel<64><<<1250, 256>>>(x_fp, p_wc + 640, p_edfp, N_FP);
    zero_fp_kernel<<<625, 256>>>();
    edge_pf_kernel<<<6250, 256>>>(pf_src, pf_dst);
    final_fp_kernel<<<625, 256>>>(bt, (float*)d_out);
}